// round 2
// baseline (speedup 1.0000x reference)
#include <cuda_runtime.h>

// TBSyntaxParser: B=8192 states, buffer [B, L=128, H=50] f32, W [3,300], b [3],
// legal_actions [B,3], buffer_index [B] i32, stack_indexes [B,3] i32.
// out [B,3] = exp(min(X@W.T + b, 10)) * legal, X = 6 gathered rows of 50.
// One warp per state; all data paths vectorized to float2 (rows are 8B-aligned),
// packed fma.rn.f32x2 for the dot products, 5-deep batched gather for MLP.

#define BB 8192
#define LL 128
#define HH 50
#define NP2 150   // 300 floats as 150 float2
#define WARPS_PER_CTA 8

__device__ __forceinline__ void ffma2(unsigned long long& acc,
                                      unsigned long long x,
                                      unsigned long long w) {
    asm("fma.rn.f32x2 %0, %1, %2, %3;" : "=l"(acc) : "l"(x), "l"(w), "l"(acc));
}

__global__ __launch_bounds__(256)
void tb_parser_kernel(const float* __restrict__ buffer,
                      const float* __restrict__ W,
                      const float* __restrict__ bvec,
                      const float* __restrict__ legal,
                      const int*   __restrict__ buf_idx,
                      const int*   __restrict__ stk_idx,
                      float*       __restrict__ out)
{
    __shared__ unsigned long long Ws2[3 * NP2];   // 900 floats = 450 u64 = 3.6 KB

    const int tid = threadIdx.x;
    const unsigned long long* Wg = (const unsigned long long*)W;  // 900 f32, 8B-aligned
    #pragma unroll
    for (int i = tid; i < 3 * NP2; i += 256) Ws2[i] = Wg[i];
    __syncthreads();

    const int warp  = tid >> 5;
    const int lane  = tid & 31;
    const int state = blockIdx.x * WARPS_PER_CTA + warp;

    const int bi = buf_idx[state];
    const int s0 = stk_idx[state * 3 + 0];
    const int s1 = stk_idx[state * 3 + 1];
    const int s2 = stk_idx[state * 3 + 2];

    const float* base = buffer + (size_t)state * (LL * HH);

    // Phase 1: batch all gather loads (MLP = 5 per lane).
    unsigned long long xv[5];
    int j2c[5];
    #pragma unroll
    for (int it = 0; it < 5; it++) {
        const int j2 = lane + it * 32;
        const bool v = (j2 < NP2);
        const int j  = v ? j2 : 0;
        j2c[it] = j;
        const int r  = j / 25;           // const-div -> mul.hi
        const int c2 = j - r * 25;
        const int row = (r == 0) ? bi
                      : (r == 1) ? bi + 1
                      : (r == 2) ? bi + 2
                      : (r == 3) ? s0
                      : (r == 4) ? s1 : s2;
        xv[it] = v ? *(const unsigned long long*)(base + row * HH + c2 * 2)
                   : 0ULL;               // x=0 -> contributes exact 0 in FMA
    }

    // Phase 2: packed FFMA2 against shared W (3 outputs).
    unsigned long long acc0 = 0ULL, acc1 = 0ULL, acc2 = 0ULL;
    #pragma unroll
    for (int it = 0; it < 5; it++) {
        const int j = j2c[it];
        ffma2(acc0, xv[it], Ws2[j]);
        ffma2(acc1, xv[it], Ws2[NP2 + j]);
        ffma2(acc2, xv[it], Ws2[2 * NP2 + j]);
    }

    // Unpack packed accumulators and fold halves.
    float a0, a1, a2;
    {
        float lo, hi;
        asm("mov.b64 {%0,%1}, %2;" : "=f"(lo), "=f"(hi) : "l"(acc0)); a0 = lo + hi;
        asm("mov.b64 {%0,%1}, %2;" : "=f"(lo), "=f"(hi) : "l"(acc1)); a1 = lo + hi;
        asm("mov.b64 {%0,%1}, %2;" : "=f"(lo), "=f"(hi) : "l"(acc2)); a2 = lo + hi;
    }

    // Warp tree-reduce.
    #pragma unroll
    for (int off = 16; off; off >>= 1) {
        a0 += __shfl_down_sync(0xffffffffu, a0, off);
        a1 += __shfl_down_sync(0xffffffffu, a1, off);
        a2 += __shfl_down_sync(0xffffffffu, a2, off);
    }

    if (lane == 0) {
        const float r0 = expf(fminf(a0 + bvec[0], 10.f)) * legal[state * 3 + 0];
        const float r1 = expf(fminf(a1 + bvec[1], 10.f)) * legal[state * 3 + 1];
        const float r2 = expf(fminf(a2 + bvec[2], 10.f)) * legal[state * 3 + 2];
        out[state * 3 + 0] = r0;
        out[state * 3 + 1] = r1;
        out[state * 3 + 2] = r2;
    }
}

extern "C" void kernel_launch(void* const* d_in, const int* in_sizes, int n_in,
                              void* d_out, int out_size)
{
    const float* buffer = (const float*)d_in[0];
    const float* W      = (const float*)d_in[1];
    const float* bvec   = (const float*)d_in[2];
    const float* legal  = (const float*)d_in[3];
    const int*   bufidx = (const int*)d_in[4];
    const int*   stkidx = (const int*)d_in[5];
    float* out = (float*)d_out;

    tb_parser_kernel<<<BB / WARPS_PER_CTA, 256>>>(buffer, W, bvec, legal,
                                                  bufidx, stkidx, out);
}

// round 4
// speedup vs baseline: 1.0728x; 1.0728x over previous
#include <cuda_runtime.h>

// TBSyntaxParser: B=8192, buffer [B,128,50] f32, W [3,300], b[3],
// legal [B,3], buffer_index [B] i32, stack_indexes [B,3] i32.
// out[B,3] = exp(min(X@W.T+b,10)) * legal, X = 6 gathered rows of 50 floats.
//
// Warp-per-state. Row-per-lane-slot gather (lanes 0..24 hold one float2 of a
// 200-B row; 6 unrolled rows), packed fma.rn.f32x2, packed-f32x2 shfl
// butterfly reduction, all dependent global loads hoisted to the top so their
// latency overlaps W staging / barrier.

#define BB   8192
#define HH   50
#define ROWE 25          // float2 per row
#define NP2  150         // 300 floats as 150 float2
#define WARPS_PER_CTA 8

typedef unsigned long long u64;

__device__ __forceinline__ void ffma2(u64& acc, u64 x, u64 w) {
    asm("fma.rn.f32x2 %0, %1, %2, %3;" : "=l"(acc) : "l"(x), "l"(w), "l"(acc));
}
__device__ __forceinline__ u64 fadd2(u64 a, u64 b) {
    u64 r;
    asm("add.rn.f32x2 %0, %1, %2;" : "=l"(r) : "l"(a), "l"(b));
    return r;
}
__device__ __forceinline__ float fold2(u64 a) {
    float lo, hi;
    asm("mov.b64 {%0,%1}, %2;" : "=f"(lo), "=f"(hi) : "l"(a));
    return lo + hi;
}
__device__ __forceinline__ u64 pack2(float lo, float hi) {
    u64 r;
    asm("mov.b64 %0, {%1,%2};" : "=l"(r) : "f"(lo), "f"(hi));
    return r;
}

__global__ __launch_bounds__(256)
void tb_parser_kernel(const float* __restrict__ buffer,
                      const float* __restrict__ W,
                      const float* __restrict__ bvec,
                      const float* __restrict__ legal,
                      const int*   __restrict__ buf_idx,
                      const int*   __restrict__ stk_idx,
                      float*       __restrict__ out)
{
    __shared__ u64 Ws2[3 * NP2];        // 900 f32 = 450 u64 = 3.6 KB

    const int tid   = threadIdx.x;
    const int warp  = tid >> 5;
    const int lane  = tid & 31;
    const int state = blockIdx.x * WARPS_PER_CTA + warp;

    // ---- issue ALL dependent scalar loads first (overlap everything) ----
    const int bi = __ldg(buf_idx + state);
    const int s0 = __ldg(stk_idx + state * 3 + 0);
    const int s1 = __ldg(stk_idx + state * 3 + 1);
    const int s2 = __ldg(stk_idx + state * 3 + 2);
    float lg = 0.f, bb = 0.f;
    if (lane < 3) {
        lg = __ldg(legal + state * 3 + lane);
        bb = __ldg(bvec + lane);
    }

    // ---- W staging: independent work hiding the idx-load latency ----
    const u64* Wg = (const u64*)W;      // 8-byte aligned
    #pragma unroll
    for (int i = tid; i < 3 * NP2; i += 256) Ws2[i] = Wg[i];

    // ---- batched gather: 6 LDG.64, one contiguous 200-B row each ----
    const float* base = buffer + (size_t)state * (128 * HH);
    const int  c  = (lane < ROWE) ? lane : (ROWE - 1);   // clamp
    const bool on = (lane < ROWE);

    u64 xv[6];
    xv[0] = *(const u64*)(base + (bi    ) * HH + c * 2);
    xv[1] = *(const u64*)(base + (bi + 1) * HH + c * 2);
    xv[2] = *(const u64*)(base + (bi + 2) * HH + c * 2);
    xv[3] = *(const u64*)(base + (s0    ) * HH + c * 2);
    xv[4] = *(const u64*)(base + (s1    ) * HH + c * 2);
    xv[5] = *(const u64*)(base + (s2    ) * HH + c * 2);
    if (!on) {
        #pragma unroll
        for (int r = 0; r < 6; r++) xv[r] = 0ULL;        // exact-zero contribution
    }

    __syncthreads();   // barrier wait overlaps gather latency

    // ---- packed dot products ----
    u64 acc0 = 0ULL, acc1 = 0ULL, acc2 = 0ULL;
    #pragma unroll
    for (int r = 0; r < 6; r++) {
        const int j = r * ROWE + c;
        ffma2(acc0, xv[r], Ws2[j]);
        ffma2(acc1, xv[r], Ws2[NP2 + j]);
        ffma2(acc2, xv[r], Ws2[2 * NP2 + j]);
    }
    // inactive lanes used lane-24's W with x=0; fold to exact 0 anyway:
    float a0 = on ? fold2(acc0) : 0.f;
    float a1 = on ? fold2(acc1) : 0.f;
    float a2 = on ? fold2(acc2) : 0.f;

    // ---- butterfly reduce: (a0,a1) packed as f32x2, a2 scalar ----
    u64  p01 = pack2(a0, a1);
    #pragma unroll
    for (int off = 16; off; off >>= 1) {
        const unsigned lo = __shfl_xor_sync(0xffffffffu, (unsigned)(p01),       off);
        const unsigned hi = __shfl_xor_sync(0xffffffffu, (unsigned)(p01 >> 32), off);
        p01 = fadd2(p01, ((u64)hi << 32) | lo);
        a2 += __shfl_xor_sync(0xffffffffu, a2, off);
    }

    if (lane < 3) {
        float lo, hi;
        asm("mov.b64 {%0,%1}, %2;" : "=f"(lo), "=f"(hi) : "l"(p01));
        const float a = (lane == 0) ? lo : (lane == 1) ? hi : a2;
        out[state * 3 + lane] = __expf(fminf(a + bb, 10.f)) * lg;
    }
}

extern "C" void kernel_launch(void* const* d_in, const int* in_sizes, int n_in,
                              void* d_out, int out_size)
{
    const float* buffer = (const float*)d_in[0];
    const float* W      = (const float*)d_in[1];
    const float* bvec   = (const float*)d_in[2];
    const float* legal  = (const float*)d_in[3];
    const int*   bufidx = (const int*)d_in[4];
    const int*   stkidx = (const int*)d_in[5];
    float* out = (float*)d_out;

    tb_parser_kernel<<<BB / WARPS_PER_CTA, 256>>>(buffer, W, bvec, legal,
                                                  bufidx, stkidx, out);
}

// round 5
// speedup vs baseline: 1.3397x; 1.2488x over previous
#include <cuda_runtime.h>

// TBSyntaxParser: B=8192, buffer [B,128,50] f32, W [3,300], b[3],
// legal [B,3], buffer_index [B] i32, stack_indexes [B,3] i32.
// out[B,3] = exp(min(X@W.T+b,10)) * legal, X = 6 gathered rows of 50 floats.
//
// TWO adjacent states per warp: 12 batched gather LDG.64 (MLP=12), shared
// per-lane W slice feeds both states' packed fma.rn.f32x2, one packed shfl
// butterfly reduces all 6 partial sums, lanes 0..5 write 6 contiguous outs.

#define HH   50
#define ROWE 25          // float2 per row
#define NP2  150         // 300 floats as 150 float2
#define CTAS 1024
#define THR  128         // 4 warps/CTA, 2 states/warp -> 8 states/CTA

typedef unsigned long long u64;

__device__ __forceinline__ void ffma2(u64& acc, u64 x, u64 w) {
    asm("fma.rn.f32x2 %0, %1, %2, %3;" : "=l"(acc) : "l"(x), "l"(w), "l"(acc));
}
__device__ __forceinline__ u64 fadd2(u64 a, u64 b) {
    u64 r;
    asm("add.rn.f32x2 %0, %1, %2;" : "=l"(r) : "l"(a), "l"(b));
    return r;
}
__device__ __forceinline__ float fold2(u64 a) {
    float lo, hi;
    asm("mov.b64 {%0,%1}, %2;" : "=f"(lo), "=f"(hi) : "l"(a));
    return lo + hi;
}
__device__ __forceinline__ u64 pack2(float lo, float hi) {
    u64 r;
    asm("mov.b64 %0, {%1,%2};" : "=l"(r) : "f"(lo), "f"(hi));
    return r;
}
__device__ __forceinline__ u64 shfl_xor64(u64 v, int off) {
    unsigned lo = (unsigned)v, hi = (unsigned)(v >> 32);
    lo = __shfl_xor_sync(0xffffffffu, lo, off);
    hi = __shfl_xor_sync(0xffffffffu, hi, off);
    return ((u64)hi << 32) | lo;
}

__global__ __launch_bounds__(THR, 8)
void tb_parser_kernel(const float* __restrict__ buffer,
                      const float* __restrict__ W,
                      const float* __restrict__ bvec,
                      const float* __restrict__ legal,
                      const int*   __restrict__ buf_idx,
                      const int*   __restrict__ stk_idx,
                      float*       __restrict__ out)
{
    __shared__ u64 Ws2[3 * NP2];        // 3.6 KB

    const int tid  = threadIdx.x;
    const int warp = tid >> 5;
    const int lane = tid & 31;
    const int gw   = blockIdx.x * 4 + warp;   // global warp id, 0..4095
    const int sA   = gw * 2;                  // two adjacent states
    // sB = sA + 1

    // ---- all dependent scalar loads first ----
    const int biA = __ldg(buf_idx + sA);
    const int biB = __ldg(buf_idx + sA + 1);
    const int aA0 = __ldg(stk_idx + sA * 3 + 0);
    const int aA1 = __ldg(stk_idx + sA * 3 + 1);
    const int aA2 = __ldg(stk_idx + sA * 3 + 2);
    const int aB0 = __ldg(stk_idx + sA * 3 + 3);
    const int aB1 = __ldg(stk_idx + sA * 3 + 4);
    const int aB2 = __ldg(stk_idx + sA * 3 + 5);
    float lg = 0.f, bb = 0.f;
    if (lane < 6) {
        lg = __ldg(legal + sA * 3 + lane);          // 6 contiguous floats
        bb = __ldg(bvec + (lane < 3 ? lane : lane - 3));
    }

    // ---- W staging (hides idx latency) ----
    const u64* Wg = (const u64*)W;
    #pragma unroll
    for (int i = tid; i < 3 * NP2; i += THR) Ws2[i] = Wg[i];

    // ---- batched gathers: 12 LDG.64 in flight ----
    const float* baseA = buffer + (size_t)sA * (128 * HH);
    const float* baseB = baseA + 128 * HH;
    const int  c  = (lane < ROWE) ? lane : (ROWE - 1);
    const bool on = (lane < ROWE);

    u64 xA[6], xB[6];
    xA[0] = *(const u64*)(baseA + (biA    ) * HH + c * 2);
    xA[1] = *(const u64*)(baseA + (biA + 1) * HH + c * 2);
    xA[2] = *(const u64*)(baseA + (biA + 2) * HH + c * 2);
    xA[3] = *(const u64*)(baseA + (aA0    ) * HH + c * 2);
    xA[4] = *(const u64*)(baseA + (aA1    ) * HH + c * 2);
    xA[5] = *(const u64*)(baseA + (aA2    ) * HH + c * 2);
    xB[0] = *(const u64*)(baseB + (biB    ) * HH + c * 2);
    xB[1] = *(const u64*)(baseB + (biB + 1) * HH + c * 2);
    xB[2] = *(const u64*)(baseB + (biB + 2) * HH + c * 2);
    xB[3] = *(const u64*)(baseB + (aB0    ) * HH + c * 2);
    xB[4] = *(const u64*)(baseB + (aB1    ) * HH + c * 2);
    xB[5] = *(const u64*)(baseB + (aB2    ) * HH + c * 2);
    if (!on) {
        #pragma unroll
        for (int r = 0; r < 6; r++) { xA[r] = 0ULL; xB[r] = 0ULL; }
    }

    __syncthreads();

    // ---- packed dot products; each W LDS feeds both states ----
    u64 a0A = 0, a1A = 0, a2A = 0, a0B = 0, a1B = 0, a2B = 0;
    #pragma unroll
    for (int r = 0; r < 6; r++) {
        const int j = r * ROWE + c;
        const u64 w0 = Ws2[j];
        const u64 w1 = Ws2[NP2 + j];
        const u64 w2 = Ws2[2 * NP2 + j];
        ffma2(a0A, xA[r], w0);  ffma2(a0B, xB[r], w0);
        ffma2(a1A, xA[r], w1);  ffma2(a1B, xB[r], w1);
        ffma2(a2A, xA[r], w2);  ffma2(a2B, xB[r], w2);
    }

    float f0A = on ? fold2(a0A) : 0.f;
    float f1A = on ? fold2(a1A) : 0.f;
    float f2A = on ? fold2(a2A) : 0.f;
    float f0B = on ? fold2(a0B) : 0.f;
    float f1B = on ? fold2(a1B) : 0.f;
    float f2B = on ? fold2(a2B) : 0.f;

    // ---- one packed butterfly reduces all six partials ----
    u64 pA = pack2(f0A, f1A);
    u64 pB = pack2(f0B, f1B);
    u64 p2 = pack2(f2A, f2B);
    #pragma unroll
    for (int off = 16; off; off >>= 1) {
        pA = fadd2(pA, shfl_xor64(pA, off));
        pB = fadd2(pB, shfl_xor64(pB, off));
        p2 = fadd2(p2, shfl_xor64(p2, off));
    }

    if (lane < 6) {
        float vA0, vA1, vB0, vB1, v2A, v2B;
        asm("mov.b64 {%0,%1}, %2;" : "=f"(vA0), "=f"(vA1) : "l"(pA));
        asm("mov.b64 {%0,%1}, %2;" : "=f"(vB0), "=f"(vB1) : "l"(pB));
        asm("mov.b64 {%0,%1}, %2;" : "=f"(v2A), "=f"(v2B) : "l"(p2));
        const float a = (lane == 0) ? vA0 : (lane == 1) ? vA1 : (lane == 2) ? v2A
                      : (lane == 3) ? vB0 : (lane == 4) ? vB1 : v2B;
        out[sA * 3 + lane] = __expf(fminf(a + bb, 10.f)) * lg;
    }
}

extern "C" void kernel_launch(void* const* d_in, const int* in_sizes, int n_in,
                              void* d_out, int out_size)
{
    const float* buffer = (const float*)d_in[0];
    const float* W      = (const float*)d_in[1];
    const float* bvec   = (const float*)d_in[2];
    const float* legal  = (const float*)d_in[3];
    const int*   bufidx = (const int*)d_in[4];
    const int*   stkidx = (const int*)d_in[5];
    float* out = (float*)d_out;

    tb_parser_kernel<<<CTAS, THR>>>(buffer, W, bvec, legal, bufidx, stkidx, out);
}

// round 6
// speedup vs baseline: 1.3527x; 1.0097x over previous
#include <cuda_runtime.h>

// TBSyntaxParser: B=8192, buffer [B,128,50] f32, W [3,300], b[3],
// legal [B,3], buffer_index [B] i32, stack_indexes [B,3] i32.
// out[B,3] = exp(min(X@W.T+b,10)) * legal, X = 6 gathered rows of 50 floats.
//
// FOUR adjacent states per warp: 24 batched gather LDG.64 (MLP=24), int4
// vectorized index loads, shared per-lane W slice feeds all 4 states' packed
// fma.rn.f32x2, 6 packed shfl butterflies reduce 12 partial sums, lanes 0..11
// write 12 contiguous outputs.

#define HH   50
#define ROWE 25          // float2 per row
#define NP2  150         // 300 floats as 150 float2
#define SPW  4           // states per warp
#define THR  128         // 4 warps/CTA -> 16 states/CTA
#define CTAS 512

typedef unsigned long long u64;

__device__ __forceinline__ void ffma2(u64& acc, u64 x, u64 w) {
    asm("fma.rn.f32x2 %0, %1, %2, %3;" : "=l"(acc) : "l"(x), "l"(w), "l"(acc));
}
__device__ __forceinline__ u64 fadd2(u64 a, u64 b) {
    u64 r;
    asm("add.rn.f32x2 %0, %1, %2;" : "=l"(r) : "l"(a), "l"(b));
    return r;
}
__device__ __forceinline__ float fold2(u64 a) {
    float lo, hi;
    asm("mov.b64 {%0,%1}, %2;" : "=f"(lo), "=f"(hi) : "l"(a));
    return lo + hi;
}
__device__ __forceinline__ u64 pack2(float lo, float hi) {
    u64 r;
    asm("mov.b64 %0, {%1,%2};" : "=l"(r) : "f"(lo), "f"(hi));
    return r;
}
__device__ __forceinline__ u64 shfl_xor64(u64 v, int off) {
    unsigned lo = (unsigned)v, hi = (unsigned)(v >> 32);
    lo = __shfl_xor_sync(0xffffffffu, lo, off);
    hi = __shfl_xor_sync(0xffffffffu, hi, off);
    return ((u64)hi << 32) | lo;
}
__device__ __forceinline__ float pick2(u64 p, int hi_sel) {
    float lo, hi;
    asm("mov.b64 {%0,%1}, %2;" : "=f"(lo), "=f"(hi) : "l"(p));
    return hi_sel ? hi : lo;
}

__global__ __launch_bounds__(THR)
void tb_parser_kernel(const float* __restrict__ buffer,
                      const float* __restrict__ W,
                      const float* __restrict__ bvec,
                      const float* __restrict__ legal,
                      const int*   __restrict__ buf_idx,
                      const int*   __restrict__ stk_idx,
                      float*       __restrict__ out)
{
    __shared__ u64 Ws2[3 * NP2];        // 3.6 KB

    const int tid  = threadIdx.x;
    const int warp = tid >> 5;
    const int lane = tid & 31;
    const int gw   = blockIdx.x * 4 + warp;   // 0..2047
    const int sA   = gw * SPW;                // 4 adjacent states

    // ---- vectorized index loads (all 16B-aligned) ----
    const int4 bi4 = __ldg((const int4*)(buf_idx + sA));
    const int4 k0  = __ldg((const int4*)(stk_idx + sA * 3));
    const int4 k1  = __ldg((const int4*)(stk_idx + sA * 3 + 4));
    const int4 k2  = __ldg((const int4*)(stk_idx + sA * 3 + 8));
    const int bia[SPW]     = { bi4.x, bi4.y, bi4.z, bi4.w };
    const int stk[SPW * 3] = { k0.x, k0.y, k0.z, k0.w,
                               k1.x, k1.y, k1.z, k1.w,
                               k2.x, k2.y, k2.z, k2.w };

    float lg = 0.f, bb = 0.f;
    if (lane < SPW * 3) {
        lg = __ldg(legal + sA * 3 + lane);       // 12 contiguous floats
        bb = __ldg(bvec + lane - (lane >= 3) * 3 - (lane >= 6) * 3 - (lane >= 9) * 3);
    }

    // ---- W staging (hides idx latency) ----
    const u64* Wg = (const u64*)W;
    #pragma unroll
    for (int i = tid; i < 3 * NP2; i += THR) Ws2[i] = Wg[i];

    // ---- batched gathers: 24 LDG.64 in flight ----
    const int  c  = (lane < ROWE) ? lane : (ROWE - 1);
    const bool on = (lane < ROWE);

    u64 xv[SPW][6];
    #pragma unroll
    for (int t = 0; t < SPW; t++) {
        const float* base = buffer + (size_t)(sA + t) * (128 * HH) + c * 2;
        xv[t][0] = *(const u64*)(base + (bia[t]    ) * HH);
        xv[t][1] = *(const u64*)(base + (bia[t] + 1) * HH);
        xv[t][2] = *(const u64*)(base + (bia[t] + 2) * HH);
        xv[t][3] = *(const u64*)(base + stk[t*3 + 0] * HH);
        xv[t][4] = *(const u64*)(base + stk[t*3 + 1] * HH);
        xv[t][5] = *(const u64*)(base + stk[t*3 + 2] * HH);
    }
    if (!on) {
        #pragma unroll
        for (int t = 0; t < SPW; t++)
            #pragma unroll
            for (int r = 0; r < 6; r++) xv[t][r] = 0ULL;
    }

    __syncthreads();

    // ---- packed dot products; each W LDS feeds 4 states ----
    u64 acc[SPW][3];
    #pragma unroll
    for (int t = 0; t < SPW; t++) { acc[t][0] = 0; acc[t][1] = 0; acc[t][2] = 0; }
    #pragma unroll
    for (int r = 0; r < 6; r++) {
        const int j = r * ROWE + c;
        const u64 w0 = Ws2[j];
        const u64 w1 = Ws2[NP2 + j];
        const u64 w2 = Ws2[2 * NP2 + j];
        #pragma unroll
        for (int t = 0; t < SPW; t++) {
            ffma2(acc[t][0], xv[t][r], w0);
            ffma2(acc[t][1], xv[t][r], w1);
            ffma2(acc[t][2], xv[t][r], w2);
        }
    }

    float f[SPW][3];
    #pragma unroll
    for (int t = 0; t < SPW; t++)
        #pragma unroll
        for (int o = 0; o < 3; o++) f[t][o] = on ? fold2(acc[t][o]) : 0.f;

    // ---- 6 packed butterflies reduce all 12 partials ----
    u64 p01[SPW];
    #pragma unroll
    for (int t = 0; t < SPW; t++) p01[t] = pack2(f[t][0], f[t][1]);
    u64 p2a = pack2(f[0][2], f[1][2]);
    u64 p2b = pack2(f[2][2], f[3][2]);
    #pragma unroll
    for (int off = 16; off; off >>= 1) {
        #pragma unroll
        for (int t = 0; t < SPW; t++) p01[t] = fadd2(p01[t], shfl_xor64(p01[t], off));
        p2a = fadd2(p2a, shfl_xor64(p2a, off));
        p2b = fadd2(p2b, shfl_xor64(p2b, off));
    }

    if (lane < SPW * 3) {
        const int t = lane / 3;      // small const-div on 12 lanes only
        const int o = lane - t * 3;
        float a;
        if (o == 2) a = (t < 2) ? pick2(p2a, t) : pick2(p2b, t - 2);
        else        a = pick2(p01[t], o);
        out[sA * 3 + lane] = __expf(fminf(a + bb, 10.f)) * lg;
    }
}

extern "C" void kernel_launch(void* const* d_in, const int* in_sizes, int n_in,
                              void* d_out, int out_size)
{
    const float* buffer = (const float*)d_in[0];
    const float* W      = (const float*)d_in[1];
    const float* bvec   = (const float*)d_in[2];
    const float* legal  = (const float*)d_in[3];
    const int*   bufidx = (const int*)d_in[4];
    const int*   stkidx = (const int*)d_in[5];
    float* out = (float*)d_out;

    tb_parser_kernel<<<CTAS, THR>>>(buffer, W, bvec, legal, bufidx, stkidx, out);
}